// round 14
// baseline (speedup 1.0000x reference)
#include <cuda_runtime.h>
#include <math.h>

#define B 64
#define C 256
#define HW 64
#define L 21
#define SLOTS 42      // max needed rows: 2 per landmark
#define PITCH 66      // EVEN: float2 row accesses stay 8B-aligned

// [f][l][c][b] window-average values, fp32, bit-matching reference f4
__device__ float g_f4[2 * L * C * B];
__device__ double g_kl[L];

// ---------------------------------------------------------------------------
// Pieces of the 32-element associative_scan tree (bit-identical to jax).
// ---------------------------------------------------------------------------
__device__ __forceinline__ void upsweep32(float (&a)[32])
{
    #pragma unroll
    for (int d = 0; d < 5; ++d) {
        #pragma unroll
        for (int i = 0; i < (32 >> (d + 1)); ++i) {
            int hi = (i << (d + 1)) + (1 << (d + 1)) - 1;
            int lo = (i << (d + 1)) + (1 << d) - 1;
            a[hi] = __fadd_rn(a[lo], a[hi]);
        }
    }
}

// completes scan32 (no incoming prefix)
__device__ __forceinline__ void downsweep32(float (&a)[32])
{
    #pragma unroll
    for (int d = 3; d >= 0; --d) {
        #pragma unroll
        for (int i = 1; i < (32 >> (d + 1)); ++i) {
            int m = (i << (d + 1)) + (1 << d) - 1;
            a[m] = __fadd_rn(a[(i << (d + 1)) - 1], a[m]);
        }
    }
}

// completes upper half of the 64-scan given carry cl (after upsweep32):
// scan64's d=5 node u[31]=cl+u[31], then down-sweep with first-mid prefix cl.
__device__ __forceinline__ void downsweep32_carry(float (&u)[32], float cl)
{
    u[31] = __fadd_rn(cl, u[31]);
    #pragma unroll
    for (int d = 4; d >= 0; --d) {
        #pragma unroll
        for (int i = 0; i < (32 >> (d + 1)); ++i) {
            int m = (i << (d + 1)) + (1 << d) - 1;
            float pre = (i == 0) ? cl : u[(i << (d + 1)) - 1];
            u[m] = __fadd_rn(pre, u[m]);
        }
    }
}

// ---------------------------------------------------------------------------
// Kernel A: one (f, b, channel) per 128-thread block. t = tid&63 = column
// (phase 1) / row-slot (phase 2); h = tid>>6 = which 32-half of the 64-deep
// scan this thread owns. Carry crosses halves via smem (bit-exact).
// ---------------------------------------------------------------------------
__global__ __launch_bounds__(128, 12) void pool_kernel(
    const float* __restrict__ f1, const float* __restrict__ f2,
    const float* __restrict__ pre1, const float* __restrict__ pre2)
{
    __shared__ __align__(16) float S1[SLOTS][PITCH];
    __shared__ float s_cl[64];                 // phase1 column carries / phase2 row carries
    __shared__ int s_left[L], s_right[L], s_down[L], s_upper[L];
    __shared__ float s_s[L];

    int bx = blockIdx.x;
    int c = bx & 255;
    int fb = bx >> 8;
    int b = fb & 63;
    int f = fb >> 6;

    const float* feat = f ? f2 : f1;
    const float* pre  = f ? pre2 : pre1;

    int tid = threadIdx.x;
    int h = tid >> 6;
    int t = tid & 63;

    // ---- phase 1 loads first (independent of smem setup) ----
    const float* p = feat + ((size_t)b * C + c) * (HW * HW) + (size_t)(h * 32) * HW + t;
    float a[32];
    #pragma unroll
    for (int j = 0; j < 32; ++j) a[j] = __ldg(p + j * HW);

    if (tid < L) {
        float x = pre[(b * L + tid) * 2 + 0];
        float y = pre[(b * L + tid) * 2 + 1];
        int left  = (int)fmaxf(x - 6.0f, 0.0f);   // clamp then trunc (non-neg)
        int right = (int)fminf(x + 6.0f, 63.0f);
        int down  = (int)fmaxf(y - 6.0f, 0.0f);
        int upper = (int)fminf(y + 6.0f, 63.0f);
        s_left[tid] = left;  s_right[tid] = right;
        s_down[tid] = down;  s_upper[tid] = upper;
        // divisor uses INCLUSIVE window (faithful quirk)
        s_s[tid] = (float)((upper - down + 1) * (right - left + 1));
    }

    upsweep32(a);
    if (h == 0) downsweep32(a);                 // lower half fully scanned
    __syncthreads();                            // landmarks visible

    // per-thread needed-row mask (broadcast LDS reads, conflict-free)
    unsigned mlo = 0, mhi = 0;
    #pragma unroll
    for (int l = 0; l < L; ++l) {
        int r = s_right[l] - 1;                 // right >= 6
        if (r < 32) mlo |= 1u << r; else mhi |= 1u << (r - 32);
        int lf = s_left[l] - 1;
        if (lf >= 0) { if (lf < 32) mlo |= 1u << lf; else mhi |= 1u << (lf - 32); }
    }
    int base_hi = __popc(mlo);
    int nR = base_hi + __popc(mhi);

    if (h == 0) {
        s_cl[t] = a[31];                        // column carry
        #pragma unroll
        for (int j = 0; j < 32; ++j) {
            if ((mlo >> j) & 1u) {
                int slot = __popc(mlo & ((1u << j) - 1u));
                S1[slot][t] = a[j];
            }
        }
    }
    __syncthreads();
    if (h == 1) {
        float cl = s_cl[t];
        downsweep32_carry(a, cl);               // a[j] = P1[32+j][t]
        #pragma unroll
        for (int j = 0; j < 32; ++j) {
            if ((mhi >> j) & 1u) {
                int slot = base_hi + __popc(mhi & ((1u << j) - 1u));
                S1[slot][t] = a[j];
            }
        }
    }
    __syncthreads();

    // ---- phase 2: row t (slot), half h; carry via s_cl ----
    bool act = t < nR;
    if (act) {
        #pragma unroll
        for (int k = 0; k < 16; ++k) {
            float2 v = *(const float2*)&S1[t][h * 32 + 2 * k];
            a[2 * k] = v.x; a[2 * k + 1] = v.y;
        }
        upsweep32(a);
        if (h == 0) {
            downsweep32(a);
            s_cl[t] = a[31];                    // row carry
            #pragma unroll
            for (int k = 0; k < 16; ++k) {
                float2 v; v.x = a[2 * k]; v.y = a[2 * k + 1];
                *(float2*)&S1[t][2 * k] = v;
            }
        }
    }
    __syncthreads();
    if (act && h == 1) {
        float cl = s_cl[t];
        downsweep32_carry(a, cl);
        #pragma unroll
        for (int k = 0; k < 16; ++k) {
            float2 v; v.x = a[2 * k]; v.y = a[2 * k + 1];
            *(float2*)&S1[t][32 + 2 * k] = v;
        }
    }
    __syncthreads();

    // ---- corners: padded P[i][j] = (i>0 && j>0) ? P2[i-1][j-1] : 0 ----
    if (tid < L) {
        int l = tid;
        int left = s_left[l], right = s_right[l];
        int down = s_down[l], upper = s_upper[l];
        int r = right - 1;
        int sr = (r < 32) ? __popc(mlo & ((1u << r) - 1u))
                          : base_hi + __popc(mhi & ((1u << (r - 32)) - 1u));
        float Pru = S1[sr][upper - 1];
        float Prd = (down > 0) ? S1[sr][down - 1] : 0.0f;
        float Plu = 0.0f, Pld = 0.0f;
        if (left > 0) {
            int lf = left - 1;
            int sl = (lf < 32) ? __popc(mlo & ((1u << lf) - 1u))
                               : base_hi + __popc(mhi & ((1u << (lf - 32)) - 1u));
            Plu = S1[sl][upper - 1];
            if (down > 0) Pld = S1[sl][down - 1];
        }
        // jax eval order: ((Pru - Plu) - Prd) + Pld, fp32
        float rect = __fadd_rn(__fsub_rn(__fsub_rn(Pru, Plu), Prd), Pld);
        float f4 = rect / s_s[l];               // IEEE fp32 div
        g_f4[(((size_t)f * L + l) * C + c) * B + b] = f4;
    }
}

// ---------------------------------------------------------------------------
// Kernel B: fp32 sequential batch mean + EMA (emulating XLA), fp64 downstream.
// One block per landmark, 256 threads = channels. [f][l][c][b] layout gives
// each thread 64 contiguous floats (16x float4). Add order ascending b.
// ---------------------------------------------------------------------------
__global__ __launch_bounds__(256) void kl_kernel(
    const float* __restrict__ fea1, const float* __restrict__ fea2)
{
    int l = blockIdx.x;
    int c = threadIdx.x;

    const float4* q1 = (const float4*)&g_f4[(((size_t)0 * L + l) * C + c) * B];
    const float4* q2 = (const float4*)&g_f4[(((size_t)1 * L + l) * C + c) * B];

    float s1 = 0.0f, s2 = 0.0f;
    #pragma unroll 4
    for (int k = 0; k < 16; ++k) {               // ascending b, sequential
        float4 v = __ldg(q1 + k);
        s1 = __fadd_rn(s1, v.x); s1 = __fadd_rn(s1, v.y);
        s1 = __fadd_rn(s1, v.z); s1 = __fadd_rn(s1, v.w);
    }
    #pragma unroll 4
    for (int k = 0; k < 16; ++k) {
        float4 v = __ldg(q2 + k);
        s2 = __fadd_rn(s2, v.x); s2 = __fadd_rn(s2, v.y);
        s2 = __fadd_rn(s2, v.z); s2 = __fadd_rn(s2, v.w);
    }
    float m1 = __fdiv_rn(s1, 64.0f);             // exact (pow2)
    float m2 = __fdiv_rn(s2, 64.0f);

    const float MM = 0.999f;
    const float OM = (float)(1.0 - 0.999);
    float fc1f = __fadd_rn(__fmul_rn(MM, m1), __fmul_rn(OM, fea1[l * C + c]));
    float fc2f = __fadd_rn(__fmul_rn(MM, m2), __fmul_rn(OM, fea2[l * C + c]));

    // ---- fp64 downstream (truth; ref's fp32 downstream error ~1e-4 rel) ----
    double fc1 = (double)fc1f, fc2 = (double)fc2f;

    __shared__ double sh[8];
    int warp = c >> 5, lane = c & 31;

    // block-max fc1
    double m = fc1;
    #pragma unroll
    for (int o = 16; o > 0; o >>= 1) {
        double tt = __shfl_xor_sync(0xffffffffu, m, o);
        m = fmax(m, tt);
    }
    if (lane == 0) sh[warp] = m;
    __syncthreads();
    m = sh[lane & 7];
    #pragma unroll
    for (int o = 4; o > 0; o >>= 1) {
        double tt = __shfl_xor_sync(0xffffffffu, m, o);
        m = fmax(m, tt);
    }

    // block-sum exp(fc1 - m)
    double se = exp(fc1 - m);
    #pragma unroll
    for (int o = 16; o > 0; o >>= 1) se += __shfl_xor_sync(0xffffffffu, se, o);
    __syncthreads();
    if (lane == 0) sh[warp] = se;
    __syncthreads();
    se = sh[lane & 7];
    #pragma unroll
    for (int o = 4; o > 0; o >>= 1) se += __shfl_xor_sync(0xffffffffu, se, o);

    double log_p = (fc1 - m) - log(se);

    // block-sum fc2
    double S2 = fc2;
    #pragma unroll
    for (int o = 16; o > 0; o >>= 1) S2 += __shfl_xor_sync(0xffffffffu, S2, o);
    __syncthreads();
    if (lane == 0) sh[warp] = S2;
    __syncthreads();
    S2 = sh[lane & 7];
    #pragma unroll
    for (int o = 4; o > 0; o >>= 1) S2 += __shfl_xor_sync(0xffffffffu, S2, o);

    double q = fc2 / S2;
    double term = (q > 0.0) ? q * (log(q) - log_p) : 0.0;

    // block-sum KL terms
    double kl = term;
    #pragma unroll
    for (int o = 16; o > 0; o >>= 1) kl += __shfl_xor_sync(0xffffffffu, kl, o);
    __syncthreads();
    if (lane == 0) sh[warp] = kl;
    __syncthreads();
    if (c == 0) {
        double tt = 0.0;
        #pragma unroll
        for (int w = 0; w < 8; ++w) tt += sh[w];
        g_kl[l] = tt;
    }
}

// ---------------------------------------------------------------------------
// Kernel C: mean over 21 landmarks -> fp32 scalar.
// ---------------------------------------------------------------------------
__global__ void final_kernel(float* __restrict__ out)
{
    int t = threadIdx.x;
    double v = (t < L) ? g_kl[t] : 0.0;
    #pragma unroll
    for (int o = 16; o > 0; o >>= 1) v += __shfl_xor_sync(0xffffffffu, v, o);
    if (t == 0) out[0] = (float)(v / 21.0);
}

extern "C" void kernel_launch(void* const* d_in, const int* in_sizes, int n_in,
                              void* d_out, int out_size)
{
    const float* f1   = (const float*)d_in[0];
    const float* f2   = (const float*)d_in[1];
    const float* pre1 = (const float*)d_in[2];
    const float* pre2 = (const float*)d_in[3];
    const float* fea1 = (const float*)d_in[4];
    const float* fea2 = (const float*)d_in[5];
    float* out = (float*)d_out;

    pool_kernel<<<2 * B * C, 128>>>(f1, f2, pre1, pre2);
    kl_kernel<<<L, 256>>>(fea1, fea2);
    final_kernel<<<1, 32>>>(out);
}

// round 15
// speedup vs baseline: 1.6303x; 1.6303x over previous
#include <cuda_runtime.h>
#include <math.h>

#define B 64
#define C 256
#define HW 64
#define L 21
#define SLOTS 42      // max needed rows: 2 per landmark
#define PITCH 66      // EVEN: float2 row accesses stay 8B-aligned

// [f][l][c][b] window-average values, fp32, bit-matching reference f4
__device__ float g_f4[2 * L * C * B];
__device__ double g_kl[L];

// ---------------------------------------------------------------------------
// Pieces of the 32-element associative_scan tree (bit-identical to jax).
// ---------------------------------------------------------------------------
__device__ __forceinline__ void upsweep32(float (&a)[32])
{
    #pragma unroll
    for (int d = 0; d < 5; ++d) {
        #pragma unroll
        for (int i = 0; i < (32 >> (d + 1)); ++i) {
            int hi = (i << (d + 1)) + (1 << (d + 1)) - 1;
            int lo = (i << (d + 1)) + (1 << d) - 1;
            a[hi] = __fadd_rn(a[lo], a[hi]);
        }
    }
}

// completes scan32 (no incoming prefix)
__device__ __forceinline__ void downsweep32(float (&a)[32])
{
    #pragma unroll
    for (int d = 3; d >= 0; --d) {
        #pragma unroll
        for (int i = 1; i < (32 >> (d + 1)); ++i) {
            int m = (i << (d + 1)) + (1 << d) - 1;
            a[m] = __fadd_rn(a[(i << (d + 1)) - 1], a[m]);
        }
    }
}

// completes upper half of the 64-scan given carry cl (after upsweep32):
// scan64's d=5 node u[31]=cl+u[31], then down-sweep with first-mid prefix cl.
__device__ __forceinline__ void downsweep32_carry(float (&u)[32], float cl)
{
    u[31] = __fadd_rn(cl, u[31]);
    #pragma unroll
    for (int d = 4; d >= 0; --d) {
        #pragma unroll
        for (int i = 0; i < (32 >> (d + 1)); ++i) {
            int m = (i << (d + 1)) + (1 << d) - 1;
            float pre = (i == 0) ? cl : u[(i << (d + 1)) - 1];
            u[m] = __fadd_rn(pre, u[m]);
        }
    }
}

// ---------------------------------------------------------------------------
// Kernel A: one (f, b, channel) per 128-thread block. t = tid&63 = column
// (phase 1) / row-slot (phase 2); h = tid>>6 = which 32-half of the 64-deep
// scan this thread owns. Carry crosses halves via smem (bit-exact).
// NOTE: no min-blocks clause — forcing 12 blocks/SM capped regs at 40 and
// spilled the scan array (R13: pool 190us, L1 84%). Spill-free > occupancy.
// ---------------------------------------------------------------------------
__global__ __launch_bounds__(128) void pool_kernel(
    const float* __restrict__ f1, const float* __restrict__ f2,
    const float* __restrict__ pre1, const float* __restrict__ pre2)
{
    __shared__ __align__(16) float S1[SLOTS][PITCH];
    __shared__ float s_cl[64];                 // phase1 column carries / phase2 row carries
    __shared__ int s_left[L], s_right[L], s_down[L], s_upper[L];
    __shared__ float s_s[L];

    int bx = blockIdx.x;
    int c = bx & 255;
    int fb = bx >> 8;
    int b = fb & 63;
    int f = fb >> 6;

    const float* feat = f ? f2 : f1;
    const float* pre  = f ? pre2 : pre1;

    int tid = threadIdx.x;
    int h = tid >> 6;
    int t = tid & 63;

    // ---- phase 1 loads first (independent of smem setup) ----
    const float* p = feat + ((size_t)b * C + c) * (HW * HW) + (size_t)(h * 32) * HW + t;
    float a[32];
    #pragma unroll
    for (int j = 0; j < 32; ++j) a[j] = __ldg(p + j * HW);

    if (tid < L) {
        float x = pre[(b * L + tid) * 2 + 0];
        float y = pre[(b * L + tid) * 2 + 1];
        int left  = (int)fmaxf(x - 6.0f, 0.0f);   // clamp then trunc (non-neg)
        int right = (int)fminf(x + 6.0f, 63.0f);
        int down  = (int)fmaxf(y - 6.0f, 0.0f);
        int upper = (int)fminf(y + 6.0f, 63.0f);
        s_left[tid] = left;  s_right[tid] = right;
        s_down[tid] = down;  s_upper[tid] = upper;
        // divisor uses INCLUSIVE window (faithful quirk)
        s_s[tid] = (float)((upper - down + 1) * (right - left + 1));
    }

    upsweep32(a);
    if (h == 0) downsweep32(a);                 // lower half fully scanned
    __syncthreads();                            // landmarks visible

    // per-thread needed-row mask (broadcast LDS reads, conflict-free)
    unsigned mlo = 0, mhi = 0;
    #pragma unroll
    for (int l = 0; l < L; ++l) {
        int r = s_right[l] - 1;                 // right >= 6
        if (r < 32) mlo |= 1u << r; else mhi |= 1u << (r - 32);
        int lf = s_left[l] - 1;
        if (lf >= 0) { if (lf < 32) mlo |= 1u << lf; else mhi |= 1u << (lf - 32); }
    }
    int base_hi = __popc(mlo);
    int nR = base_hi + __popc(mhi);

    if (h == 0) {
        s_cl[t] = a[31];                        // column carry
        #pragma unroll
        for (int j = 0; j < 32; ++j) {
            if ((mlo >> j) & 1u) {
                int slot = __popc(mlo & ((1u << j) - 1u));
                S1[slot][t] = a[j];
            }
        }
    }
    __syncthreads();
    if (h == 1) {
        float cl = s_cl[t];
        downsweep32_carry(a, cl);               // a[j] = P1[32+j][t]
        #pragma unroll
        for (int j = 0; j < 32; ++j) {
            if ((mhi >> j) & 1u) {
                int slot = base_hi + __popc(mhi & ((1u << j) - 1u));
                S1[slot][t] = a[j];
            }
        }
    }
    __syncthreads();

    // ---- phase 2: row t (slot), half h; carry via s_cl ----
    bool act = t < nR;
    if (act) {
        #pragma unroll
        for (int k = 0; k < 16; ++k) {
            float2 v = *(const float2*)&S1[t][h * 32 + 2 * k];
            a[2 * k] = v.x; a[2 * k + 1] = v.y;
        }
        upsweep32(a);
        if (h == 0) {
            downsweep32(a);
            s_cl[t] = a[31];                    // row carry
            #pragma unroll
            for (int k = 0; k < 16; ++k) {
                float2 v; v.x = a[2 * k]; v.y = a[2 * k + 1];
                *(float2*)&S1[t][2 * k] = v;
            }
        }
    }
    __syncthreads();
    if (act && h == 1) {
        float cl = s_cl[t];
        downsweep32_carry(a, cl);
        #pragma unroll
        for (int k = 0; k < 16; ++k) {
            float2 v; v.x = a[2 * k]; v.y = a[2 * k + 1];
            *(float2*)&S1[t][32 + 2 * k] = v;
        }
    }
    __syncthreads();

    // ---- corners: padded P[i][j] = (i>0 && j>0) ? P2[i-1][j-1] : 0 ----
    if (tid < L) {
        int l = tid;
        int left = s_left[l], right = s_right[l];
        int down = s_down[l], upper = s_upper[l];
        int r = right - 1;
        int sr = (r < 32) ? __popc(mlo & ((1u << r) - 1u))
                          : base_hi + __popc(mhi & ((1u << (r - 32)) - 1u));
        float Pru = S1[sr][upper - 1];
        float Prd = (down > 0) ? S1[sr][down - 1] : 0.0f;
        float Plu = 0.0f, Pld = 0.0f;
        if (left > 0) {
            int lf = left - 1;
            int sl = (lf < 32) ? __popc(mlo & ((1u << lf) - 1u))
                               : base_hi + __popc(mhi & ((1u << (lf - 32)) - 1u));
            Plu = S1[sl][upper - 1];
            if (down > 0) Pld = S1[sl][down - 1];
        }
        // jax eval order: ((Pru - Plu) - Prd) + Pld, fp32
        float rect = __fadd_rn(__fsub_rn(__fsub_rn(Pru, Plu), Prd), Pld);
        float f4 = rect / s_s[l];               // IEEE fp32 div
        g_f4[(((size_t)f * L + l) * C + c) * B + b] = f4;
    }
}

// ---------------------------------------------------------------------------
// Kernel B: fp32 sequential batch mean + EMA (emulating XLA), fp64 downstream.
// One block per landmark, 256 threads = channels. [f][l][c][b] layout gives
// each thread 64 contiguous floats (16x float4), loads fully front-batched.
// Add order ascending b (bit-exact).
// ---------------------------------------------------------------------------
__global__ __launch_bounds__(256) void kl_kernel(
    const float* __restrict__ fea1, const float* __restrict__ fea2)
{
    int l = blockIdx.x;
    int c = threadIdx.x;

    const float4* q1 = (const float4*)&g_f4[(((size_t)0 * L + l) * C + c) * B];
    const float4* q2 = (const float4*)&g_f4[(((size_t)1 * L + l) * C + c) * B];

    float4 w1[16], w2[16];
    #pragma unroll
    for (int k = 0; k < 16; ++k) w1[k] = __ldg(q1 + k);
    #pragma unroll
    for (int k = 0; k < 16; ++k) w2[k] = __ldg(q2 + k);

    float s1 = 0.0f, s2 = 0.0f;
    #pragma unroll
    for (int k = 0; k < 16; ++k) {               // ascending b, sequential
        s1 = __fadd_rn(s1, w1[k].x); s1 = __fadd_rn(s1, w1[k].y);
        s1 = __fadd_rn(s1, w1[k].z); s1 = __fadd_rn(s1, w1[k].w);
    }
    #pragma unroll
    for (int k = 0; k < 16; ++k) {
        s2 = __fadd_rn(s2, w2[k].x); s2 = __fadd_rn(s2, w2[k].y);
        s2 = __fadd_rn(s2, w2[k].z); s2 = __fadd_rn(s2, w2[k].w);
    }
    float m1 = __fdiv_rn(s1, 64.0f);             // exact (pow2)
    float m2 = __fdiv_rn(s2, 64.0f);

    const float MM = 0.999f;
    const float OM = (float)(1.0 - 0.999);
    float fc1f = __fadd_rn(__fmul_rn(MM, m1), __fmul_rn(OM, fea1[l * C + c]));
    float fc2f = __fadd_rn(__fmul_rn(MM, m2), __fmul_rn(OM, fea2[l * C + c]));

    // ---- fp64 downstream (truth; ref's fp32 downstream error ~1e-4 rel) ----
    double fc1 = (double)fc1f, fc2 = (double)fc2f;

    __shared__ double sh[8];
    int warp = c >> 5, lane = c & 31;

    // block-max fc1
    double m = fc1;
    #pragma unroll
    for (int o = 16; o > 0; o >>= 1) {
        double tt = __shfl_xor_sync(0xffffffffu, m, o);
        m = fmax(m, tt);
    }
    if (lane == 0) sh[warp] = m;
    __syncthreads();
    m = sh[lane & 7];
    #pragma unroll
    for (int o = 4; o > 0; o >>= 1) {
        double tt = __shfl_xor_sync(0xffffffffu, m, o);
        m = fmax(m, tt);
    }

    // block-sum exp(fc1 - m)
    double se = exp(fc1 - m);
    #pragma unroll
    for (int o = 16; o > 0; o >>= 1) se += __shfl_xor_sync(0xffffffffu, se, o);
    __syncthreads();
    if (lane == 0) sh[warp] = se;
    __syncthreads();
    se = sh[lane & 7];
    #pragma unroll
    for (int o = 4; o > 0; o >>= 1) se += __shfl_xor_sync(0xffffffffu, se, o);

    double log_p = (fc1 - m) - log(se);

    // block-sum fc2
    double S2 = fc2;
    #pragma unroll
    for (int o = 16; o > 0; o >>= 1) S2 += __shfl_xor_sync(0xffffffffu, S2, o);
    __syncthreads();
    if (lane == 0) sh[warp] = S2;
    __syncthreads();
    S2 = sh[lane & 7];
    #pragma unroll
    for (int o = 4; o > 0; o >>= 1) S2 += __shfl_xor_sync(0xffffffffu, S2, o);

    double q = fc2 / S2;
    double term = (q > 0.0) ? q * (log(q) - log_p) : 0.0;

    // block-sum KL terms
    double kl = term;
    #pragma unroll
    for (int o = 16; o > 0; o >>= 1) kl += __shfl_xor_sync(0xffffffffu, kl, o);
    __syncthreads();
    if (lane == 0) sh[warp] = kl;
    __syncthreads();
    if (c == 0) {
        double tt = 0.0;
        #pragma unroll
        for (int w = 0; w < 8; ++w) tt += sh[w];
        g_kl[l] = tt;
    }
}

// ---------------------------------------------------------------------------
// Kernel C: mean over 21 landmarks -> fp32 scalar.
// ---------------------------------------------------------------------------
__global__ void final_kernel(float* __restrict__ out)
{
    int t = threadIdx.x;
    double v = (t < L) ? g_kl[t] : 0.0;
    #pragma unroll
    for (int o = 16; o > 0; o >>= 1) v += __shfl_xor_sync(0xffffffffu, v, o);
    if (t == 0) out[0] = (float)(v / 21.0);
}

extern "C" void kernel_launch(void* const* d_in, const int* in_sizes, int n_in,
                              void* d_out, int out_size)
{
    const float* f1   = (const float*)d_in[0];
    const float* f2   = (const float*)d_in[1];
    const float* pre1 = (const float*)d_in[2];
    const float* pre2 = (const float*)d_in[3];
    const float* fea1 = (const float*)d_in[4];
    const float* fea2 = (const float*)d_in[5];
    float* out = (float*)d_out;

    pool_kernel<<<2 * B * C, 128>>>(f1, f2, pre1, pre2);
    kl_kernel<<<L, 256>>>(fea1, fea2);
    final_kernel<<<1, 32>>>(out);
}

// round 16
// speedup vs baseline: 1.8064x; 1.1081x over previous
#include <cuda_runtime.h>
#include <math.h>

#define B 64
#define C 256
#define HW 64
#define L 21
#define PITCH 66      // EVEN: float2 row accesses stay 8B-aligned

// [f][l][c][b] window-average values, fp32, bit-matching reference f4
__device__ float g_f4[2 * L * C * B];
__device__ double g_kl[L];

// ---------------------------------------------------------------------------
// Pieces of the 32-element associative_scan tree (bit-identical to jax).
// ---------------------------------------------------------------------------
__device__ __forceinline__ void upsweep32(float (&a)[32])
{
    #pragma unroll
    for (int d = 0; d < 5; ++d) {
        #pragma unroll
        for (int i = 0; i < (32 >> (d + 1)); ++i) {
            int hi = (i << (d + 1)) + (1 << (d + 1)) - 1;
            int lo = (i << (d + 1)) + (1 << d) - 1;
            a[hi] = __fadd_rn(a[lo], a[hi]);
        }
    }
}

// completes scan32 (no incoming prefix)
__device__ __forceinline__ void downsweep32(float (&a)[32])
{
    #pragma unroll
    for (int d = 3; d >= 0; --d) {
        #pragma unroll
        for (int i = 1; i < (32 >> (d + 1)); ++i) {
            int m = (i << (d + 1)) + (1 << d) - 1;
            a[m] = __fadd_rn(a[(i << (d + 1)) - 1], a[m]);
        }
    }
}

// completes upper half of the 64-scan given carry cl (after upsweep32):
// scan64's d=5 node u[31]=cl+u[31], then down-sweep with first-mid prefix cl.
__device__ __forceinline__ void downsweep32_carry(float (&u)[32], float cl)
{
    u[31] = __fadd_rn(cl, u[31]);
    #pragma unroll
    for (int d = 4; d >= 0; --d) {
        #pragma unroll
        for (int i = 0; i < (32 >> (d + 1)); ++i) {
            int m = (i << (d + 1)) + (1 << d) - 1;
            float pre = (i == 0) ? cl : u[(i << (d + 1)) - 1];
            u[m] = __fadd_rn(pre, u[m]);
        }
    }
}

// ---------------------------------------------------------------------------
// Kernel A: one (f, b, channel) per 128-thread block. t = tid&63 = column
// (phase 1) / row (phase 2); h = tid>>6 = which 32-half of the 64-deep scan
// this thread owns. Carry crosses halves via smem (bit-exact).
// NO masks/popc (R14: alu pipe 56% = binder): full 64-row smem array,
// unconditional phase-1 writeback, s_flag[] row selection, direct indexing.
// ---------------------------------------------------------------------------
__global__ __launch_bounds__(128) void pool_kernel(
    const float* __restrict__ f1, const float* __restrict__ f2,
    const float* __restrict__ pre1, const float* __restrict__ pre2)
{
    __shared__ __align__(16) float S1[HW][PITCH];   // full integral-image tile
    __shared__ float s_cl[64];                 // phase1 column carries / phase2 row carries
    __shared__ int s_flag[HW];                 // rows needed by corner extraction
    __shared__ int s_left[L], s_right[L], s_down[L], s_upper[L];
    __shared__ float s_s[L];

    int bx = blockIdx.x;
    int c = bx & 255;
    int fb = bx >> 8;
    int b = fb & 63;
    int f = fb >> 6;

    const float* feat = f ? f2 : f1;
    const float* pre  = f ? pre2 : pre1;

    int tid = threadIdx.x;
    int h = tid >> 6;
    int t = tid & 63;

    // ---- phase 1 loads first (independent of smem setup) ----
    const float* p = feat + ((size_t)b * C + c) * (HW * HW) + (size_t)(h * 32) * HW + t;
    float a[32];
    #pragma unroll
    for (int j = 0; j < 32; ++j) a[j] = __ldg(p + j * HW);

    if (h == 0) s_flag[t] = 0;
    if (tid < L) {
        float x = pre[(b * L + tid) * 2 + 0];
        float y = pre[(b * L + tid) * 2 + 1];
        int left  = (int)fmaxf(x - 6.0f, 0.0f);   // clamp then trunc (non-neg)
        int right = (int)fminf(x + 6.0f, 63.0f);
        int down  = (int)fmaxf(y - 6.0f, 0.0f);
        int upper = (int)fminf(y + 6.0f, 63.0f);
        s_left[tid] = left;  s_right[tid] = right;
        s_down[tid] = down;  s_upper[tid] = upper;
        // divisor uses INCLUSIVE window (faithful quirk)
        s_s[tid] = (float)((upper - down + 1) * (right - left + 1));
    }

    upsweep32(a);
    if (h == 0) downsweep32(a);                 // lower half fully scanned
    __syncthreads();                            // flags zeroed, landmarks visible

    // mark rows needed for corners (benign same-value races)
    if (tid < L) {
        s_flag[s_right[tid] - 1] = 1;           // right >= 6
        if (s_left[tid] > 0) s_flag[s_left[tid] - 1] = 1;
    }

    if (h == 0) {
        s_cl[t] = a[31];                        // column carry
        #pragma unroll
        for (int j = 0; j < 32; ++j) S1[j][t] = a[j];
    }
    __syncthreads();                            // s_cl + flags visible
    if (h == 1) {
        float cl = s_cl[t];
        downsweep32_carry(a, cl);               // a[j] = P1[32+j][t]
        #pragma unroll
        for (int j = 0; j < 32; ++j) S1[32 + j][t] = a[j];
    }
    __syncthreads();

    // ---- phase 2: row t (if needed), half h; carry via s_cl ----
    bool act = s_flag[t] != 0;
    if (act) {
        #pragma unroll
        for (int k = 0; k < 16; ++k) {
            float2 v = *(const float2*)&S1[t][h * 32 + 2 * k];
            a[2 * k] = v.x; a[2 * k + 1] = v.y;
        }
        upsweep32(a);
        if (h == 0) {
            downsweep32(a);
            s_cl[t] = a[31];                    // row carry
            #pragma unroll
            for (int k = 0; k < 16; ++k) {
                float2 v; v.x = a[2 * k]; v.y = a[2 * k + 1];
                *(float2*)&S1[t][2 * k] = v;
            }
        }
    }
    __syncthreads();
    if (act && h == 1) {
        float cl = s_cl[t];
        downsweep32_carry(a, cl);
        #pragma unroll
        for (int k = 0; k < 16; ++k) {
            float2 v; v.x = a[2 * k]; v.y = a[2 * k + 1];
            *(float2*)&S1[t][32 + 2 * k] = v;
        }
    }
    __syncthreads();

    // ---- corners: padded P[i][j] = (i>0 && j>0) ? P2[i-1][j-1] : 0 ----
    if (tid < L) {
        int l = tid;
        int left = s_left[l], right = s_right[l];
        int down = s_down[l], upper = s_upper[l];
        float Pru = S1[right - 1][upper - 1];   // right,upper >= 6
        float Prd = (down > 0) ? S1[right - 1][down - 1] : 0.0f;
        float Plu = 0.0f, Pld = 0.0f;
        if (left > 0) {
            Plu = S1[left - 1][upper - 1];
            if (down > 0) Pld = S1[left - 1][down - 1];
        }
        // jax eval order: ((Pru - Plu) - Prd) + Pld, fp32
        float rect = __fadd_rn(__fsub_rn(__fsub_rn(Pru, Plu), Prd), Pld);
        float f4 = rect / s_s[l];               // IEEE fp32 div
        g_f4[(((size_t)f * L + l) * C + c) * B + b] = f4;
    }
}

// ---------------------------------------------------------------------------
// Kernel B: fp32 sequential batch mean + EMA (emulating XLA), fp64 downstream.
// One block per landmark, 256 threads = channels. [f][l][c][b] layout gives
// each thread 64 contiguous floats. No register arrays (R14 spilled);
// interleaved dual chains, full unroll. Add order ascending b (bit-exact).
// ---------------------------------------------------------------------------
__global__ __launch_bounds__(256) void kl_kernel(
    const float* __restrict__ fea1, const float* __restrict__ fea2)
{
    int l = blockIdx.x;
    int c = threadIdx.x;

    const float4* q1 = (const float4*)&g_f4[(((size_t)0 * L + l) * C + c) * B];
    const float4* q2 = (const float4*)&g_f4[(((size_t)1 * L + l) * C + c) * B];

    float s1 = 0.0f, s2 = 0.0f;
    #pragma unroll
    for (int k = 0; k < 16; ++k) {               // ascending b, sequential
        float4 v1 = __ldg(q1 + k);
        float4 v2 = __ldg(q2 + k);
        s1 = __fadd_rn(s1, v1.x); s1 = __fadd_rn(s1, v1.y);
        s1 = __fadd_rn(s1, v1.z); s1 = __fadd_rn(s1, v1.w);
        s2 = __fadd_rn(s2, v2.x); s2 = __fadd_rn(s2, v2.y);
        s2 = __fadd_rn(s2, v2.z); s2 = __fadd_rn(s2, v2.w);
    }
    float m1 = __fdiv_rn(s1, 64.0f);             // exact (pow2)
    float m2 = __fdiv_rn(s2, 64.0f);

    const float MM = 0.999f;
    const float OM = (float)(1.0 - 0.999);
    float fc1f = __fadd_rn(__fmul_rn(MM, m1), __fmul_rn(OM, fea1[l * C + c]));
    float fc2f = __fadd_rn(__fmul_rn(MM, m2), __fmul_rn(OM, fea2[l * C + c]));

    // ---- fp64 downstream (truth; ref's fp32 downstream error ~1e-4 rel) ----
    double fc1 = (double)fc1f, fc2 = (double)fc2f;

    __shared__ double sh[8];
    int warp = c >> 5, lane = c & 31;

    // block-max fc1
    double m = fc1;
    #pragma unroll
    for (int o = 16; o > 0; o >>= 1) {
        double tt = __shfl_xor_sync(0xffffffffu, m, o);
        m = fmax(m, tt);
    }
    if (lane == 0) sh[warp] = m;
    __syncthreads();
    m = sh[lane & 7];
    #pragma unroll
    for (int o = 4; o > 0; o >>= 1) {
        double tt = __shfl_xor_sync(0xffffffffu, m, o);
        m = fmax(m, tt);
    }

    // block-sum exp(fc1 - m)
    double se = exp(fc1 - m);
    #pragma unroll
    for (int o = 16; o > 0; o >>= 1) se += __shfl_xor_sync(0xffffffffu, se, o);
    __syncthreads();
    if (lane == 0) sh[warp] = se;
    __syncthreads();
    se = sh[lane & 7];
    #pragma unroll
    for (int o = 4; o > 0; o >>= 1) se += __shfl_xor_sync(0xffffffffu, se, o);

    double log_p = (fc1 - m) - log(se);

    // block-sum fc2
    double S2 = fc2;
    #pragma unroll
    for (int o = 16; o > 0; o >>= 1) S2 += __shfl_xor_sync(0xffffffffu, S2, o);
    __syncthreads();
    if (lane == 0) sh[warp] = S2;
    __syncthreads();
    S2 = sh[lane & 7];
    #pragma unroll
    for (int o = 4; o > 0; o >>= 1) S2 += __shfl_xor_sync(0xffffffffu, S2, o);

    double q = fc2 / S2;
    double term = (q > 0.0) ? q * (log(q) - log_p) : 0.0;

    // block-sum KL terms
    double kl = term;
    #pragma unroll
    for (int o = 16; o > 0; o >>= 1) kl += __shfl_xor_sync(0xffffffffu, kl, o);
    __syncthreads();
    if (lane == 0) sh[warp] = kl;
    __syncthreads();
    if (c == 0) {
        double tt = 0.0;
        #pragma unroll
        for (int w = 0; w < 8; ++w) tt += sh[w];
        g_kl[l] = tt;
    }
}

// ---------------------------------------------------------------------------
// Kernel C: mean over 21 landmarks -> fp32 scalar.
// ---------------------------------------------------------------------------
__global__ void final_kernel(float* __restrict__ out)
{
    int t = threadIdx.x;
    double v = (t < L) ? g_kl[t] : 0.0;
    #pragma unroll
    for (int o = 16; o > 0; o >>= 1) v += __shfl_xor_sync(0xffffffffu, v, o);
    if (t == 0) out[0] = (float)(v / 21.0);
}

extern "C" void kernel_launch(void* const* d_in, const int* in_sizes, int n_in,
                              void* d_out, int out_size)
{
    const float* f1   = (const float*)d_in[0];
    const float* f2   = (const float*)d_in[1];
    const float* pre1 = (const float*)d_in[2];
    const float* pre2 = (const float*)d_in[3];
    const float* fea1 = (const float*)d_in[4];
    const float* fea2 = (const float*)d_in[5];
    float* out = (float*)d_out;

    pool_kernel<<<2 * B * C, 128>>>(f1, f2, pre1, pre2);
    kl_kernel<<<L, 256>>>(fea1, fea2);
    final_kernel<<<1, 32>>>(out);
}